// round 16
// baseline (speedup 1.0000x reference)
#include <cuda_runtime.h>
#include <cuda_fp16.h>

#define D_MODEL 1024
#define SEQ     2048
#define BATCH   2
#define NHEAD   16
#define DHEAD   64
#define HB      32
#define MROWS   4096

typedef unsigned int u32;
typedef unsigned short u16;

#define XN ((size_t)MROWS * D_MODEL)     // 4194304
#define WN ((size_t)D_MODEL * D_MODEL)   // 1048576

// ---- device-global scratch (allocation-free) ----
__device__ u16 g_xh[3 * XN];             // fp16 inputs (q,k,v)
__device__ u16 g_wh[3 * WN];             // fp16 weights
__device__ u16 g_qh[(size_t)HB * SEQ * DHEAD];
__device__ u16 g_kh[(size_t)HB * SEQ * DHEAD];
__device__ u16 g_vh[(size_t)HB * SEQ * DHEAD];
__device__ u16 g_ps[(size_t)HB * SEQ * SEQ];          // unnormalized exp, fp16
__device__ float g_attn_fb[(size_t)HB * SEQ * SEQ];   // fallback sinks
__device__ float g_ctx_fb[(size_t)MROWS * D_MODEL];

// ---- PTX primitives ----
__device__ __forceinline__ void ldm_x4(u32 r[4], u32 addr) {
    asm volatile("ldmatrix.sync.aligned.m8n8.x4.shared.b16 {%0,%1,%2,%3}, [%4];"
                 : "=r"(r[0]), "=r"(r[1]), "=r"(r[2]), "=r"(r[3]) : "r"(addr));
}
__device__ __forceinline__ void ldm_x4t(u32 r[4], u32 addr) {
    asm volatile("ldmatrix.sync.aligned.m8n8.x4.trans.shared.b16 {%0,%1,%2,%3}, [%4];"
                 : "=r"(r[0]), "=r"(r[1]), "=r"(r[2]), "=r"(r[3]) : "r"(addr));
}
__device__ __forceinline__ void mma16816(float d[4], const u32 a[4], const u32 b[2]) {
    asm volatile("mma.sync.aligned.m16n8k16.row.col.f32.f16.f16.f32 "
                 "{%0,%1,%2,%3}, {%4,%5,%6,%7}, {%8,%9}, {%0,%1,%2,%3};"
                 : "+f"(d[0]), "+f"(d[1]), "+f"(d[2]), "+f"(d[3])
                 : "r"(a[0]), "r"(a[1]), "r"(a[2]), "r"(a[3]), "r"(b[0]), "r"(b[1]));
}
__device__ __forceinline__ u32 smem_u32(const void* p) {
    return (u32)__cvta_generic_to_shared(p);
}
__device__ __forceinline__ void cpa16(u32 d, const void* s) {
    asm volatile("cp.async.cg.shared.global [%0], [%1], 16;" :: "r"(d), "l"(s));
}
__device__ __forceinline__ void cpa_commit() {
    asm volatile("cp.async.commit_group;" ::: "memory");
}
__device__ __forceinline__ void cpa_wait1() {
    asm volatile("cp.async.wait_group 1;" ::: "memory");
}
__device__ __forceinline__ void cpa_wait0() {
    asm volatile("cp.async.wait_group 0;" ::: "memory");
}
__device__ __forceinline__ u32 pack_hi(float x, float y) {
    __half2 h2 = __floats2half2_rn(x, y);
    return *reinterpret_cast<u32*>(&h2);
}
__device__ __forceinline__ float2 unpack_h2(u32 v) {
    __half2 h2 = *reinterpret_cast<__half2*>(&v);
    return __half22float2(h2);
}

// ============================================================================
// Convert kernel: fp32 -> fp16, grid.z = {Xq,Xk,Xv,Wq,Wk,Wv}. MLP=2, 16B STG.
// ============================================================================
__global__ __launch_bounds__(256) void conv_kernel(
    const float* __restrict__ Xq, const float* __restrict__ Xk,
    const float* __restrict__ Xv,
    const float* __restrict__ Wq, const float* __restrict__ Wk,
    const float* __restrict__ Wv)
{
    const int z = blockIdx.z;
    const float* srcs[6] = {Xq, Xk, Xv, Wq, Wk, Wv};
    const float* src = srcs[z];
    u16* dst = (z < 3) ? (g_xh + (size_t)z * XN) : (g_wh + (size_t)(z - 3) * WN);
    const size_t n8 = ((z < 3) ? XN : WN) >> 3;

    for (size_t i = blockIdx.x * blockDim.x + threadIdx.x; i < n8;
         i += (size_t)gridDim.x * blockDim.x) {
        float4 a = *reinterpret_cast<const float4*>(src + i * 8);
        float4 b = *reinterpret_cast<const float4*>(src + i * 8 + 4);
        uint4 o;
        o.x = pack_hi(a.x, a.y);
        o.y = pack_hi(a.z, a.w);
        o.z = pack_hi(b.x, b.y);
        o.w = pack_hi(b.z, b.w);
        *reinterpret_cast<uint4*>(dst + i * 8) = o;
    }
}

// ============================================================================
// Projection (grid.z = Q/K/V): fp16 GEMM, cp.async 3-stage pipeline, BK=32.
// ============================================================================
#define PJ_STR 40
#define PSTG_A 0
#define PSTG_B 10240
#define PSTG   20480
#define PROJ_SMEM (3 * PSTG)   // 61440
#define NKT 32

__device__ __forceinline__ void proj_issue(u32 sbase,
    const u16* X, const u16* Wt, int m0c, int n0c, int k0, int tid)
{
#pragma unroll
    for (int j = 0; j < 2; j++) {
        int id  = tid + j * 256;
        int row = id >> 2, ch = id & 3;
        cpa16(sbase + PSTG_A + row * 80 + ch * 16,
              X + (size_t)(m0c + row) * D_MODEL + k0 + ch * 8);
    }
#pragma unroll
    for (int j = 0; j < 2; j++) {
        int id  = tid + j * 256;
        int row = id >> 2, ch = id & 3;
        cpa16(sbase + PSTG_B + row * 80 + ch * 16,
              Wt + (size_t)(n0c + row) * D_MODEL + k0 + ch * 8);
    }
}

__global__ __launch_bounds__(256, 2) void proj_kernel(
    const float* __restrict__ bq, const float* __restrict__ bk,
    const float* __restrict__ bv)
{
    const int which = blockIdx.z;
    const u16* X  = g_xh + (size_t)which * XN;
    const u16* Wt = g_wh + (size_t)which * WN;
    const float* bias = (which == 0) ? bq : (which == 1) ? bk : bv;
    u16* outh = (which == 0) ? g_qh : (which == 1) ? g_kh : g_vh;

    extern __shared__ char psm[];
    const u32 base = smem_u32(psm);

    const int tid = threadIdx.x;
    const int lane = tid & 31;
    const int wid = tid >> 5;
    const int wm = wid >> 1, wn = wid & 1;
    const int m0c = blockIdx.y * 128;
    const int n0c = blockIdx.x * 128;

    float acc[2][8][4];
#pragma unroll
    for (int mf = 0; mf < 2; mf++)
#pragma unroll
        for (int nf = 0; nf < 8; nf++)
#pragma unroll
            for (int q = 0; q < 4; q++) acc[mf][nf][q] = 0.0f;

    proj_issue(base, X, Wt, m0c, n0c, 0, tid);
    cpa_commit();
    proj_issue(base + PSTG, X, Wt, m0c, n0c, 32, tid);
    cpa_commit();

    for (int i = 0; i < NKT; i++) {
        cpa_wait1();
        __syncthreads();
        if (i + 2 < NKT)
            proj_issue(base + ((i + 2) % 3) * PSTG, X, Wt, m0c, n0c,
                       (i + 2) * 32, tid);
        cpa_commit();

        const u32 sb = base + (i % 3) * PSTG;

#pragma unroll
        for (int ks = 0; ks < 32; ks += 16) {
            u32 ah[2][4];
#pragma unroll
            for (int mf = 0; mf < 2; mf++) {
                u32 off = ((wm * 32 + mf * 16 + (lane & 15)) * PJ_STR +
                           ks + ((lane >> 4) << 3)) * 2;
                ldm_x4(ah[mf], sb + PSTG_A + off);
            }
#pragma unroll
            for (int pf = 0; pf < 4; pf++) {
                u32 off = ((wn * 64 + pf * 16 + (lane & 15)) * PJ_STR +
                           ks + ((lane >> 4) << 3)) * 2;
                u32 bh4[4];
                ldm_x4(bh4, sb + PSTG_B + off);
                u32 beh[2] = {bh4[0], bh4[2]}, boh[2] = {bh4[1], bh4[3]};
#pragma unroll
                for (int mf = 0; mf < 2; mf++) {
                    mma16816(acc[mf][2 * pf],     ah[mf], beh);
                    mma16816(acc[mf][2 * pf + 1], ah[mf], boh);
                }
            }
        }
    }

#pragma unroll
    for (int mf = 0; mf < 2; mf++) {
#pragma unroll
        for (int nf = 0; nf < 8; nf++) {
            int col = n0c + wn * 64 + nf * 8 + ((lane & 3) << 1);
            float b0 = bias[col], b1 = bias[col + 1];
            int h = col >> 6, d = col & 63;
#pragma unroll
            for (int half = 0; half < 2; half++) {
                int gi = m0c + wm * 32 + mf * 16 + (lane >> 2) + half * 8;
                int b_ = gi >> 11, s_ = gi & (SEQ - 1);
                float x = acc[mf][nf][half * 2]     + b0;
                float y = acc[mf][nf][half * 2 + 1] + b1;
                size_t idx = ((size_t)(h * BATCH + b_) * SEQ + s_) * DHEAD + d;
                *reinterpret_cast<u32*>(&outh[idx]) = pack_hi(x, y);
            }
        }
    }
}

// ============================================================================
// Two-pass flash attention, p-materialized.
// Pass 1: s = qh·kh, p = exp(s*scale) -> fp16 gmem (g_ps); l = rowsum.
// Pass 2: cp.async p + V; ldm p fragments are directly PV A-operands;
//         attn = p * (1/l) (unpack+mul, no exp); ctx = (P·V) * (1/l).
// ============================================================================
#define NT      32
#define STG1    9216
#define ST_P    0
#define ST_V    18432
#define STG2    27648
#define ATTN_SMEM (3 * STG2)   // 82944

__device__ __forceinline__ void issue_stage1(u32 sbase, const u16* kh, int tid) {
#pragma unroll
    for (int j = 0; j < 2; j++) {
        int id  = tid + j * 256;
        int row = id >> 3, ch = id & 7;
        cpa16(sbase + row * 144 + ch * 16, kh + (size_t)row * 64 + ch * 8);
    }
}
// Pass-2 stage: P tile (128 rows x 64 keys fp16, stride 72) + V tile (64 x 64).
__device__ __forceinline__ void issue_stage2(u32 sbase,
    const u16* pn, const u16* vh, int tid)
{
#pragma unroll
    for (int j = 0; j < 4; j++) {
        int id  = tid + j * 256;          // 1024 chunks
        int row = id >> 3, ch = id & 7;
        cpa16(sbase + ST_P + row * 144 + ch * 16,
              pn + (size_t)row * SEQ + ch * 8);
    }
#pragma unroll
    for (int j = 0; j < 2; j++) {
        int id  = tid + j * 256;          // 512 chunks
        int row = id >> 3, ch = id & 7;
        cpa16(sbase + ST_V + row * 144 + ch * 16,
              vh + (size_t)row * 64 + ch * 8);
    }
}

__global__ __launch_bounds__(256, 2) void attn_kernel(
    float* __restrict__ attn_out, float* __restrict__ ctx_out)
{
    extern __shared__ char sm[];
    const u32 base = smem_u32(sm);

    const int tid = threadIdx.x;
    const int lane = tid & 31;
    const int wid = tid >> 5;
    const int m0w = wid * 16;
    const int n  = blockIdx.y;
    const int r0 = blockIdx.x * 128;
    const float scale = 0.125f;

    const size_t nbase = (size_t)n * SEQ * DHEAD;
    float* An = attn_out + (size_t)n * SEQ * SEQ;
    u16*  Pn  = g_ps + (size_t)n * SEQ * SEQ;

    // ---- Q -> transient smem -> register fragments ----
    {
        const u16* qh = g_qh + nbase + (size_t)r0 * DHEAD;
#pragma unroll
        for (int j = 0; j < 4; j++) {
            int id = tid + j * 256;
            int row = id >> 3, ch = id & 7;
            *reinterpret_cast<uint4*>(sm + row * 144 + ch * 16) =
                *reinterpret_cast<const uint4*>(qh + (size_t)row * 64 + ch * 8);
        }
    }
    __syncthreads();
    u32 qh4[4][4];
#pragma unroll
    for (int q = 0; q < 4; q++) {
        u32 off = ((m0w + (lane & 15)) * 72 + q * 16 + ((lane >> 4) << 3)) * 2;
        ldm_x4(qh4[q], base + off);
    }
    __syncthreads();

    const u16* gkh = g_kh + nbase;
    const u16* gvh = g_vh + nbase;

    // ============ PASS 1: p = exp(qh·kh·scale) -> g_ps; l = rowsum ==========
    issue_stage1(base, gkh, tid);
    cpa_commit();
    issue_stage1(base + STG1, gkh + 64 * DHEAD, tid);
    cpa_commit();

    float lsum0 = 0.0f, lsum1 = 0.0f;

    for (int i = 0; i < NT; i++) {
        cpa_wait1();
        __syncthreads();
        if (i + 2 < NT)
            issue_stage1(base + ((i + 2) % 3) * STG1,
                         gkh + (size_t)(i + 2) * 64 * DHEAD, tid);
        cpa_commit();

        const u32 sb = base + (i % 3) * STG1;

        float sacc[8][4];
#pragma unroll
        for (int nf = 0; nf < 8; nf++)
#pragma unroll
            for (int q = 0; q < 4; q++) sacc[nf][q] = 0.0f;

#pragma unroll
        for (int q = 0; q < 4; q++) {
            int ks = q * 16;
#pragma unroll
            for (int pf = 0; pf < 4; pf++) {
                u32 boff = ((pf * 16 + (lane & 15)) * 72 +
                            ks + ((lane >> 4) << 3)) * 2;
                u32 bh4[4];
                ldm_x4(bh4, sb + boff);
                u32 beh[2] = {bh4[0], bh4[2]}, boh[2] = {bh4[1], bh4[3]};
                mma16816(sacc[2 * pf],     qh4[q], beh);
                mma16816(sacc[2 * pf + 1], qh4[q], boh);
            }
        }

        u16* pr0 = Pn + (size_t)(r0 + m0w + (lane >> 2)) * SEQ + i * 64;
        u16* pr1 = pr0 + 8 * SEQ;
#pragma unroll
        for (int nf = 0; nf < 8; nf++) {
            float e0 = __expf(sacc[nf][0] * scale);
            float e1 = __expf(sacc[nf][1] * scale);
            float e2 = __expf(sacc[nf][2] * scale);
            float e3 = __expf(sacc[nf][3] * scale);
            int col = nf * 8 + ((lane & 3) << 1);
            *reinterpret_cast<u32*>(pr0 + col) = pack_hi(e0, e1);
            *reinterpret_cast<u32*>(pr1 + col) = pack_hi(e2, e3);
            lsum0 += e0 + e1;
            lsum1 += e2 + e3;
        }
    }

    lsum0 += __shfl_xor_sync(0xffffffffu, lsum0, 1);
    lsum0 += __shfl_xor_sync(0xffffffffu, lsum0, 2);
    lsum1 += __shfl_xor_sync(0xffffffffu, lsum1, 1);
    lsum1 += __shfl_xor_sync(0xffffffffu, lsum1, 2);
    const float li0 = 1.0f / lsum0;
    const float li1 = 1.0f / lsum1;

    cpa_wait0();
    __syncthreads();   // p stores visible CTA-wide; stage bufs free

    // ============ PASS 2: attn = p*linv; ctx = (P·V)*linv ===================
    const u16* Pr0 = Pn + (size_t)r0 * SEQ;
    issue_stage2(base, Pr0, gvh, tid);
    cpa_commit();
    issue_stage2(base + STG2, Pr0 + 64, gvh + 64 * DHEAD, tid);
    cpa_commit();

    float cacc[8][4];
#pragma unroll
    for (int nf = 0; nf < 8; nf++)
#pragma unroll
        for (int q = 0; q < 4; q++) cacc[nf][q] = 0.0f;

    for (int i = 0; i < NT; i++) {
        cpa_wait1();
        __syncthreads();
        if (i + 2 < NT)
            issue_stage2(base + ((i + 2) % 3) * STG2,
                         Pr0 + (i + 2) * 64,
                         gvh + (size_t)(i + 2) * 64 * DHEAD, tid);
        cpa_commit();

        const u32 sb = base + (i % 3) * STG2;

        float* anr0 = An + (size_t)(r0 + m0w + (lane >> 2)) * SEQ + i * 64;
        float* anr1 = anr0 + 8 * SEQ;
        const int c0 = (lane & 3) << 1;

#pragma unroll
        for (int t = 0; t < 4; t++) {
            u32 pf4[4];
            u32 poff = ((m0w + (lane & 15)) * 72 + t * 16 +
                        ((lane >> 4) << 3)) * 2;
            ldm_x4(pf4, sb + ST_P + poff);

            // attn write: normalized p
            float2 v0 = unpack_h2(pf4[0]);
            float2 v1 = unpack_h2(pf4[1]);
            float2 v2 = unpack_h2(pf4[2]);
            float2 v3 = unpack_h2(pf4[3]);
            *reinterpret_cast<float2*>(anr0 + t * 16 + c0) =
                make_float2(v0.x * li0, v0.y * li0);
            *reinterpret_cast<float2*>(anr1 + t * 16 + c0) =
                make_float2(v1.x * li1, v1.y * li1);
            *reinterpret_cast<float2*>(anr0 + t * 16 + 8 + c0) =
                make_float2(v2.x * li0, v2.y * li0);
            *reinterpret_cast<float2*>(anr1 + t * 16 + 8 + c0) =
                make_float2(v3.x * li1, v3.y * li1);

            // PV: fragments are the A-operands directly
#pragma unroll
            for (int dp = 0; dp < 4; dp++) {
                u32 voff = ((t * 16 + (lane & 15)) * 72 +
                            dp * 16 + ((lane >> 4) << 3)) * 2;
                u32 vh4[4];
                ldm_x4t(vh4, sb + ST_V + voff);
                u32 b0h[2] = {vh4[0], vh4[1]}, b1h[2] = {vh4[2], vh4[3]};
                mma16816(cacc[2 * dp],     pf4, b0h);
                mma16816(cacc[2 * dp + 1], pf4, b1h);
            }
        }
    }

    // ---- ctx epilogue: scale by 1/l ----
    const int h = n >> 1, b_ = n & 1;
    const int s0 = r0 + m0w + (lane >> 2);
#pragma unroll
    for (int nf = 0; nf < 8; nf++) {
        int d = h * 64 + nf * 8 + ((lane & 3) << 1);
        *reinterpret_cast<float2*>(
            &ctx_out[((size_t)b_ * SEQ + s0) * D_MODEL + d]) =
            make_float2(cacc[nf][0] * li0, cacc[nf][1] * li0);
        *reinterpret_cast<float2*>(
            &ctx_out[((size_t)b_ * SEQ + s0 + 8) * D_MODEL + d]) =
            make_float2(cacc[nf][2] * li1, cacc[nf][3] * li1);
    }
}

// ============================================================================
extern "C" void kernel_launch(void* const* d_in, const int* in_sizes, int n_in,
                              void* d_out, int out_size)
{
    const float* query = (const float*)d_in[0];
    const float* key_  = (const float*)d_in[1];
    const float* value = (const float*)d_in[2];
    const float* Wq = (const float*)d_in[3];
    const float* bq = (const float*)d_in[4];
    const float* Wk = (const float*)d_in[5];
    const float* bk = (const float*)d_in[6];
    const float* Wv = (const float*)d_in[7];
    const float* bv = (const float*)d_in[8];

    cudaFuncSetAttribute(proj_kernel, cudaFuncAttributeMaxDynamicSharedMemorySize,
                         PROJ_SMEM);
    cudaFuncSetAttribute(attn_kernel, cudaFuncAttributeMaxDynamicSharedMemorySize,
                         ATTN_SMEM);

    const long long CTX_N  = (long long)MROWS * D_MODEL;   // 4194304
    const long long ATTN_N = (long long)HB * SEQ * SEQ;    // 134217728
    float* ctx_out;
    float* attn_out;
    void* sym;
    if ((long long)out_size >= CTX_N + ATTN_N) {
        ctx_out  = (float*)d_out;
        attn_out = (float*)d_out + CTX_N;
    } else if ((long long)out_size == ATTN_N) {
        attn_out = (float*)d_out;
        cudaGetSymbolAddress(&sym, g_ctx_fb);
        ctx_out = (float*)sym;
    } else {
        ctx_out = (float*)d_out;
        cudaGetSymbolAddress(&sym, g_attn_fb);
        attn_out = (float*)sym;
    }

    dim3 cgrid(512, 1, 6);
    conv_kernel<<<cgrid, 256>>>(query, key_, value, Wq, Wk, Wv);

    dim3 pgrid(D_MODEL / 128, MROWS / 128, 3);   // (8, 32, 3) fused Q/K/V
    proj_kernel<<<pgrid, 256, PROJ_SMEM>>>(bq, bk, bv);

    dim3 agrid(SEQ / 128, HB);                   // (16, 32)
    attn_kernel<<<agrid, 256, ATTN_SMEM>>>(attn_out, ctx_out);
}

// round 17
// speedup vs baseline: 1.1485x; 1.1485x over previous
#include <cuda_runtime.h>
#include <cuda_fp16.h>

#define D_MODEL 1024
#define SEQ     2048
#define BATCH   2
#define NHEAD   16
#define DHEAD   64
#define HB      32
#define MROWS   4096

typedef unsigned int u32;
typedef unsigned short u16;

#define XN ((size_t)MROWS * D_MODEL)     // 4194304
#define WN ((size_t)D_MODEL * D_MODEL)   // 1048576

// ---- device-global scratch (allocation-free) ----
__device__ u16 g_xh[3 * XN];             // fp16 inputs (q,k,v)
__device__ u16 g_wh[3 * WN];             // fp16 weights
__device__ u16 g_qh[(size_t)HB * SEQ * DHEAD];
__device__ u16 g_kh[(size_t)HB * SEQ * DHEAD];
__device__ u16 g_vh[(size_t)HB * SEQ * DHEAD];
__device__ float g_attn_fb[(size_t)HB * SEQ * SEQ];   // fallback sinks
__device__ float g_ctx_fb[(size_t)MROWS * D_MODEL];

// ---- PTX primitives ----
__device__ __forceinline__ void ldm_x4(u32 r[4], u32 addr) {
    asm volatile("ldmatrix.sync.aligned.m8n8.x4.shared.b16 {%0,%1,%2,%3}, [%4];"
                 : "=r"(r[0]), "=r"(r[1]), "=r"(r[2]), "=r"(r[3]) : "r"(addr));
}
__device__ __forceinline__ void ldm_x4t(u32 r[4], u32 addr) {
    asm volatile("ldmatrix.sync.aligned.m8n8.x4.trans.shared.b16 {%0,%1,%2,%3}, [%4];"
                 : "=r"(r[0]), "=r"(r[1]), "=r"(r[2]), "=r"(r[3]) : "r"(addr));
}
__device__ __forceinline__ void mma16816(float d[4], const u32 a[4], const u32 b[2]) {
    asm volatile("mma.sync.aligned.m16n8k16.row.col.f32.f16.f16.f32 "
                 "{%0,%1,%2,%3}, {%4,%5,%6,%7}, {%8,%9}, {%0,%1,%2,%3};"
                 : "+f"(d[0]), "+f"(d[1]), "+f"(d[2]), "+f"(d[3])
                 : "r"(a[0]), "r"(a[1]), "r"(a[2]), "r"(a[3]), "r"(b[0]), "r"(b[1]));
}
__device__ __forceinline__ u32 smem_u32(const void* p) {
    return (u32)__cvta_generic_to_shared(p);
}
__device__ __forceinline__ void cpa16(u32 d, const void* s) {
    asm volatile("cp.async.cg.shared.global [%0], [%1], 16;" :: "r"(d), "l"(s));
}
__device__ __forceinline__ void cpa_commit() {
    asm volatile("cp.async.commit_group;" ::: "memory");
}
__device__ __forceinline__ void cpa_wait1() {
    asm volatile("cp.async.wait_group 1;" ::: "memory");
}
__device__ __forceinline__ void cpa_wait0() {
    asm volatile("cp.async.wait_group 0;" ::: "memory");
}
__device__ __forceinline__ u32 pack_hi(float x, float y) {
    __half2 h2 = __floats2half2_rn(x, y);
    return *reinterpret_cast<u32*>(&h2);
}
// exp(s*0.125) == 2^(s*0.125*log2(e)); EX2 directly, no FMUL via __expf path
#define EXSCALE 0.18033688011112042f
__device__ __forceinline__ float ex2(float x) {
    float r;
    asm("ex2.approx.ftz.f32 %0, %1;" : "=f"(r) : "f"(x));
    return r;
}

// ============================================================================
// Convert kernel: fp32 -> fp16, grid.z = {Xq,Xk,Xv,Wq,Wk,Wv}. MLP=2, 16B STG.
// ============================================================================
__global__ __launch_bounds__(256) void conv_kernel(
    const float* __restrict__ Xq, const float* __restrict__ Xk,
    const float* __restrict__ Xv,
    const float* __restrict__ Wq, const float* __restrict__ Wk,
    const float* __restrict__ Wv)
{
    const int z = blockIdx.z;
    const float* srcs[6] = {Xq, Xk, Xv, Wq, Wk, Wv};
    const float* src = srcs[z];
    u16* dst = (z < 3) ? (g_xh + (size_t)z * XN) : (g_wh + (size_t)(z - 3) * WN);
    const size_t n8 = ((z < 3) ? XN : WN) >> 3;

    for (size_t i = blockIdx.x * blockDim.x + threadIdx.x; i < n8;
         i += (size_t)gridDim.x * blockDim.x) {
        float4 a = *reinterpret_cast<const float4*>(src + i * 8);
        float4 b = *reinterpret_cast<const float4*>(src + i * 8 + 4);
        uint4 o;
        o.x = pack_hi(a.x, a.y);
        o.y = pack_hi(a.z, a.w);
        o.z = pack_hi(b.x, b.y);
        o.w = pack_hi(b.z, b.w);
        *reinterpret_cast<uint4*>(dst + i * 8) = o;
    }
}

// ============================================================================
// Projection (grid.z = Q/K/V): fp16 GEMM, cp.async 3-stage pipeline, BK=32.
// C = X @ W^T + b -> fp16, head-permuted [H*B, S, Dh].
// ============================================================================
#define PJ_STR 40
#define PSTG_A 0
#define PSTG_B 10240
#define PSTG   20480
#define PROJ_SMEM (3 * PSTG)   // 61440
#define NKT 32

__device__ __forceinline__ void proj_issue(u32 sbase,
    const u16* X, const u16* Wt, int m0c, int n0c, int k0, int tid)
{
#pragma unroll
    for (int j = 0; j < 2; j++) {
        int id  = tid + j * 256;
        int row = id >> 2, ch = id & 3;
        cpa16(sbase + PSTG_A + row * 80 + ch * 16,
              X + (size_t)(m0c + row) * D_MODEL + k0 + ch * 8);
    }
#pragma unroll
    for (int j = 0; j < 2; j++) {
        int id  = tid + j * 256;
        int row = id >> 2, ch = id & 3;
        cpa16(sbase + PSTG_B + row * 80 + ch * 16,
              Wt + (size_t)(n0c + row) * D_MODEL + k0 + ch * 8);
    }
}

__global__ __launch_bounds__(256, 2) void proj_kernel(
    const float* __restrict__ bq, const float* __restrict__ bk,
    const float* __restrict__ bv)
{
    const int which = blockIdx.z;
    const u16* X  = g_xh + (size_t)which * XN;
    const u16* Wt = g_wh + (size_t)which * WN;
    const float* bias = (which == 0) ? bq : (which == 1) ? bk : bv;
    u16* outh = (which == 0) ? g_qh : (which == 1) ? g_kh : g_vh;

    extern __shared__ char psm[];
    const u32 base = smem_u32(psm);

    const int tid = threadIdx.x;
    const int lane = tid & 31;
    const int wid = tid >> 5;
    const int wm = wid >> 1, wn = wid & 1;
    const int m0c = blockIdx.y * 128;
    const int n0c = blockIdx.x * 128;

    float acc[2][8][4];
#pragma unroll
    for (int mf = 0; mf < 2; mf++)
#pragma unroll
        for (int nf = 0; nf < 8; nf++)
#pragma unroll
            for (int q = 0; q < 4; q++) acc[mf][nf][q] = 0.0f;

    proj_issue(base, X, Wt, m0c, n0c, 0, tid);
    cpa_commit();
    proj_issue(base + PSTG, X, Wt, m0c, n0c, 32, tid);
    cpa_commit();

    for (int i = 0; i < NKT; i++) {
        cpa_wait1();
        __syncthreads();
        if (i + 2 < NKT)
            proj_issue(base + ((i + 2) % 3) * PSTG, X, Wt, m0c, n0c,
                       (i + 2) * 32, tid);
        cpa_commit();

        const u32 sb = base + (i % 3) * PSTG;

#pragma unroll
        for (int ks = 0; ks < 32; ks += 16) {
            u32 ah[2][4];
#pragma unroll
            for (int mf = 0; mf < 2; mf++) {
                u32 off = ((wm * 32 + mf * 16 + (lane & 15)) * PJ_STR +
                           ks + ((lane >> 4) << 3)) * 2;
                ldm_x4(ah[mf], sb + PSTG_A + off);
            }
#pragma unroll
            for (int pf = 0; pf < 4; pf++) {
                u32 off = ((wn * 64 + pf * 16 + (lane & 15)) * PJ_STR +
                           ks + ((lane >> 4) << 3)) * 2;
                u32 bh4[4];
                ldm_x4(bh4, sb + PSTG_B + off);
                u32 beh[2] = {bh4[0], bh4[2]}, boh[2] = {bh4[1], bh4[3]};
#pragma unroll
                for (int mf = 0; mf < 2; mf++) {
                    mma16816(acc[mf][2 * pf],     ah[mf], beh);
                    mma16816(acc[mf][2 * pf + 1], ah[mf], boh);
                }
            }
        }
    }

#pragma unroll
    for (int mf = 0; mf < 2; mf++) {
#pragma unroll
        for (int nf = 0; nf < 8; nf++) {
            int col = n0c + wn * 64 + nf * 8 + ((lane & 3) << 1);
            float b0 = bias[col], b1 = bias[col + 1];
            int h = col >> 6, d = col & 63;
#pragma unroll
            for (int half = 0; half < 2; half++) {
                int gi = m0c + wm * 32 + mf * 16 + (lane >> 2) + half * 8;
                int b_ = gi >> 11, s_ = gi & (SEQ - 1);
                float x = acc[mf][nf][half * 2]     + b0;
                float y = acc[mf][nf][half * 2 + 1] + b1;
                size_t idx = ((size_t)(h * BATCH + b_) * SEQ + s_) * DHEAD + d;
                *reinterpret_cast<u32*>(&outh[idx]) = pack_hi(x, y);
            }
        }
    }
}

// ============================================================================
// Two-pass flash attention (fp16 mma.sync, cp.async pipeline) — R15 structure.
// Pass 1: l = rowsum(ex2(s*EXSCALE))          (1-term fp16 QK)
// Pass 2: s = qh·kh, p = ex2(...)*linv -> attn write; ctx += ph·vh.
// ============================================================================
#define NT      32
#define STG1    9216
#define STG2    18432
#define ST_KH   0
#define ST_VH   9216
#define ATTN_SMEM (3 * STG2)   // 55296

__device__ __forceinline__ void issue_stage1(u32 sbase, const u16* kh, int tid) {
#pragma unroll
    for (int j = 0; j < 2; j++) {
        int id  = tid + j * 256;
        int row = id >> 3, ch = id & 7;
        cpa16(sbase + row * 144 + ch * 16, kh + (size_t)row * 64 + ch * 8);
    }
}
__device__ __forceinline__ void issue_stage2(u32 sbase,
    const u16* kh, const u16* vh, int tid)
{
    const u16* srcs[2] = {kh, vh};
#pragma unroll
    for (int tns = 0; tns < 2; tns++) {
#pragma unroll
        for (int j = 0; j < 2; j++) {
            int id  = tid + j * 256;
            int row = id >> 3, ch = id & 7;
            cpa16(sbase + tns * 9216 + row * 144 + ch * 16,
                  srcs[tns] + (size_t)row * 64 + ch * 8);
        }
    }
}

__global__ __launch_bounds__(256, 2) void attn_kernel(
    float* __restrict__ attn_out, float* __restrict__ ctx_out)
{
    extern __shared__ char sm[];
    const u32 base = smem_u32(sm);

    const int tid = threadIdx.x;
    const int lane = tid & 31;
    const int wid = tid >> 5;
    const int m0w = wid * 16;
    const int n  = blockIdx.y;
    const int r0 = blockIdx.x * 128;

    const size_t nbase = (size_t)n * SEQ * DHEAD;
    float* An = attn_out + (size_t)n * SEQ * SEQ;

    // ---- Q -> transient smem -> register fragments ----
    {
        const u16* qh = g_qh + nbase + (size_t)r0 * DHEAD;
#pragma unroll
        for (int j = 0; j < 4; j++) {
            int id = tid + j * 256;
            int row = id >> 3, ch = id & 7;
            *reinterpret_cast<uint4*>(sm + row * 144 + ch * 16) =
                *reinterpret_cast<const uint4*>(qh + (size_t)row * 64 + ch * 8);
        }
    }
    __syncthreads();
    u32 qh4[4][4];
#pragma unroll
    for (int q = 0; q < 4; q++) {
        u32 off = ((m0w + (lane & 15)) * 72 + q * 16 + ((lane >> 4) << 3)) * 2;
        ldm_x4(qh4[q], base + off);
    }
    __syncthreads();

    const u16* gkh = g_kh + nbase;
    const u16* gvh = g_vh + nbase;

    // =================== PASS 1: row sums ===================================
    issue_stage1(base, gkh, tid);
    cpa_commit();
    issue_stage1(base + STG1, gkh + 64 * DHEAD, tid);
    cpa_commit();

    float lsum0 = 0.0f, lsum1 = 0.0f;

    for (int i = 0; i < NT; i++) {
        cpa_wait1();
        __syncthreads();
        if (i + 2 < NT)
            issue_stage1(base + ((i + 2) % 3) * STG1,
                         gkh + (size_t)(i + 2) * 64 * DHEAD, tid);
        cpa_commit();

        const u32 sb = base + (i % 3) * STG1;

        float sacc[8][4];
#pragma unroll
        for (int nf = 0; nf < 8; nf++)
#pragma unroll
            for (int q = 0; q < 4; q++) sacc[nf][q] = 0.0f;

#pragma unroll
        for (int q = 0; q < 4; q++) {
            int ks = q * 16;
#pragma unroll
            for (int pf = 0; pf < 4; pf++) {
                u32 boff = ((pf * 16 + (lane & 15)) * 72 +
                            ks + ((lane >> 4) << 3)) * 2;
                u32 bh4[4];
                ldm_x4(bh4, sb + boff);
                u32 beh[2] = {bh4[0], bh4[2]}, boh[2] = {bh4[1], bh4[3]};
                mma16816(sacc[2 * pf],     qh4[q], beh);
                mma16816(sacc[2 * pf + 1], qh4[q], boh);
            }
        }
#pragma unroll
        for (int nf = 0; nf < 8; nf++) {
            lsum0 += ex2(sacc[nf][0] * EXSCALE) + ex2(sacc[nf][1] * EXSCALE);
            lsum1 += ex2(sacc[nf][2] * EXSCALE) + ex2(sacc[nf][3] * EXSCALE);
        }
    }

    lsum0 += __shfl_xor_sync(0xffffffffu, lsum0, 1);
    lsum0 += __shfl_xor_sync(0xffffffffu, lsum0, 2);
    lsum1 += __shfl_xor_sync(0xffffffffu, lsum1, 1);
    lsum1 += __shfl_xor_sync(0xffffffffu, lsum1, 2);
    const float li0 = 1.0f / lsum0;
    const float li1 = 1.0f / lsum1;

    cpa_wait0();
    __syncthreads();

    // =================== PASS 2: attn + ctx ================================
    issue_stage2(base, gkh, gvh, tid);
    cpa_commit();
    issue_stage2(base + STG2, gkh + 64 * DHEAD, gvh + 64 * DHEAD, tid);
    cpa_commit();

    float cacc[8][4];
#pragma unroll
    for (int nf = 0; nf < 8; nf++)
#pragma unroll
        for (int q = 0; q < 4; q++) cacc[nf][q] = 0.0f;

    for (int i = 0; i < NT; i++) {
        cpa_wait1();
        __syncthreads();
        if (i + 2 < NT) {
            size_t o = (size_t)(i + 2) * 64 * DHEAD;
            issue_stage2(base + ((i + 2) % 3) * STG2, gkh + o, gvh + o, tid);
        }
        cpa_commit();

        const u32 sb = base + (i % 3) * STG2;

        float sacc[8][4];
#pragma unroll
        for (int nf = 0; nf < 8; nf++)
#pragma unroll
            for (int q = 0; q < 4; q++) sacc[nf][q] = 0.0f;

        // ---- QK: qh · kh (1-term) ----
#pragma unroll
        for (int q = 0; q < 4; q++) {
            int ks = q * 16;
#pragma unroll
            for (int pf = 0; pf < 4; pf++) {
                u32 boff = ((pf * 16 + (lane & 15)) * 72 +
                            ks + ((lane >> 4) << 3)) * 2;
                u32 bh4[4];
                ldm_x4(bh4, sb + ST_KH + boff);
                u32 beh[2] = {bh4[0], bh4[2]}, boh[2] = {bh4[1], bh4[3]};
                mma16816(sacc[2 * pf],     qh4[q], beh);
                mma16816(sacc[2 * pf + 1], qh4[q], boh);
            }
        }

        // ---- normalized p + attn write ----
        float* anr0 = An + (size_t)(r0 + m0w + (lane >> 2)) * SEQ + i * 64;
        float* anr1 = anr0 + 8 * SEQ;
#pragma unroll
        for (int nf = 0; nf < 8; nf++) {
            float p0 = ex2(sacc[nf][0] * EXSCALE) * li0;
            float p1 = ex2(sacc[nf][1] * EXSCALE) * li0;
            float p2 = ex2(sacc[nf][2] * EXSCALE) * li1;
            float p3 = ex2(sacc[nf][3] * EXSCALE) * li1;
            sacc[nf][0] = p0; sacc[nf][1] = p1;
            sacc[nf][2] = p2; sacc[nf][3] = p3;
            int col = nf * 8 + ((lane & 3) << 1);
            *reinterpret_cast<float2*>(anr0 + col) = make_float2(p0, p1);
            *reinterpret_cast<float2*>(anr1 + col) = make_float2(p2, p3);
        }

        // ---- PV: ph · vh (1-term) ----
#pragma unroll
        for (int t = 0; t < 4; t++) {
            u32 ph4[4];
            ph4[0] = pack_hi(sacc[2 * t][0],     sacc[2 * t][1]);
            ph4[1] = pack_hi(sacc[2 * t][2],     sacc[2 * t][3]);
            ph4[2] = pack_hi(sacc[2 * t + 1][0], sacc[2 * t + 1][1]);
            ph4[3] = pack_hi(sacc[2 * t + 1][2], sacc[2 * t + 1][3]);
#pragma unroll
            for (int dp = 0; dp < 4; dp++) {
                u32 voff = ((t * 16 + (lane & 15)) * 72 +
                            dp * 16 + ((lane >> 4) << 3)) * 2;
                u32 vh4[4];
                ldm_x4t(vh4, sb + ST_VH + voff);
                u32 b0h[2] = {vh4[0], vh4[1]}, b1h[2] = {vh4[2], vh4[3]};
                mma16816(cacc[2 * dp],     ph4, b0h);
                mma16816(cacc[2 * dp + 1], ph4, b1h);
            }
        }
    }

    // ---- ctx epilogue ----
    const int h = n >> 1, b_ = n & 1;
    const int s0 = r0 + m0w + (lane >> 2);
#pragma unroll
    for (int nf = 0; nf < 8; nf++) {
        int d = h * 64 + nf * 8 + ((lane & 3) << 1);
        *reinterpret_cast<float2*>(
            &ctx_out[((size_t)b_ * SEQ + s0) * D_MODEL + d]) =
            make_float2(cacc[nf][0], cacc[nf][1]);
        *reinterpret_cast<float2*>(
            &ctx_out[((size_t)b_ * SEQ + s0 + 8) * D_MODEL + d]) =
            make_float2(cacc[nf][2], cacc[nf][3]);
    }
}

// ============================================================================
extern "C" void kernel_launch(void* const* d_in, const int* in_sizes, int n_in,
                              void* d_out, int out_size)
{
    const float* query = (const float*)d_in[0];
    const float* key_  = (const float*)d_in[1];
    const float* value = (const float*)d_in[2];
    const float* Wq = (const float*)d_in[3];
    const float* bq = (const float*)d_in[4];
    const float* Wk = (const float*)d_in[5];
    const float* bk = (const float*)d_in[6];
    const float* Wv = (const float*)d_in[7];
    const float* bv = (const float*)d_in[8];

    cudaFuncSetAttribute(proj_kernel, cudaFuncAttributeMaxDynamicSharedMemorySize,
                         PROJ_SMEM);
    cudaFuncSetAttribute(attn_kernel, cudaFuncAttributeMaxDynamicSharedMemorySize,
                         ATTN_SMEM);

    const long long CTX_N  = (long long)MROWS * D_MODEL;   // 4194304
    const long long ATTN_N = (long long)HB * SEQ * SEQ;    // 134217728
    float* ctx_out;
    float* attn_out;
    void* sym;
    if ((long long)out_size >= CTX_N + ATTN_N) {
        ctx_out  = (float*)d_out;
        attn_out = (float*)d_out + CTX_N;
    } else if ((long long)out_size == ATTN_N) {
        attn_out = (float*)d_out;
        cudaGetSymbolAddress(&sym, g_ctx_fb);
        ctx_out = (float*)sym;
    } else {
        ctx_out = (float*)d_out;
        cudaGetSymbolAddress(&sym, g_attn_fb);
        attn_out = (float*)sym;
    }

    dim3 cgrid(512, 1, 6);
    conv_kernel<<<cgrid, 256>>>(query, key_, value, Wq, Wk, Wv);

    dim3 pgrid(D_MODEL / 128, MROWS / 128, 3);   // (8, 32, 3) fused Q/K/V
    proj_kernel<<<pgrid, 256, PROJ_SMEM>>>(bq, bk, bv);

    dim3 agrid(SEQ / 128, HB);                   // (16, 32)
    attn_kernel<<<agrid, 256, ATTN_SMEM>>>(attn_out, ctx_out);
}